// round 15
// baseline (speedup 1.0000x reference)
#include <cuda_runtime.h>
#include <cstdint>

#define T_STEPS 64
#define BB      8
#define IN_DIM  256
#define HH      512
#define H3      1536
#define NBLK    128
#define NTHR    512

// ---------------- output offsets (floats) ----------------
#define OUT_V      0ull
#define OUT_H      4096ull
#define OUT_DUF    8192ull
#define OUT_TEF    2105344ull
#define OUT_TEMAT  2109440ull
#define OUT_OUTS   4206592ull
#define OUT_DUS    4468736ull
#define OUT_MODS   138686464ull
#define OUT_SS     138735616ull
#define OUT_MS     138736128ull
#define OUT_RS     138736640ull

// ---------------- smem layout (float index) ----------------
#define S_TEM  0        /* [32][512] trace_E rows (batch-local) */
#define S_ZW   16384    /* [68][512] zo rows (non-gate) / 4 zo + 64 mod rows (gate) */
#define S_H    51200    /* [512] h_b */
#define S_HFW  51712    /* [512] hfw_b */
#define S_TE   52224    /* [512] te_b */
#define S_WX   52736    /* [1536] wx(t) */
#define S_FWP  54272    /* [32][4] */
#define S_MOD  54400    /* [96] pad 128 */
#define S_ZV   54528    /* [96] zo row values for stats */
#define S_DV   54624    /* [32] dv row values */
#define S_SCAL 54656    /* r,s,m */
#define S_RED  54672    /* [32] */
#define SMEM_FLOATS 54704
// prologue overlay: sX [0,1024) + wtile [1024,14848) inside S_TEM

// ---------------- device globals ----------------
__device__ float    g_wx[T_STEPS * BB * H3];
__device__ float    g_whbuf[2][BB * H3];
__device__ unsigned g_lineA[NBLK][32];   // [0]=flag, [1]=s1 bits, [2]=s2 bits
__device__ unsigned g_lineB[BB][32];     // [0]=flag, [1]=r, [2]=s, [3]=m

// ---------------- helpers ----------------
__device__ __forceinline__ unsigned ld_acq(const unsigned* p) {
    unsigned v;
    asm volatile("ld.global.acquire.gpu.b32 %0, [%1];" : "=r"(v) : "l"(p) : "memory");
    return v;
}
__device__ __forceinline__ void st_rel(unsigned* p, unsigned v) {
    asm volatile("st.global.release.gpu.b32 [%0], %1;" :: "l"(p), "r"(v) : "memory");
}
__device__ __forceinline__ void wait_line(unsigned* p, unsigned tgt) {
    if (threadIdx.x == 0) { while (ld_acq(p) < tgt) {} }
    __syncthreads();
}
__device__ __forceinline__ float sigm(float x) { return 1.f / (1.f + __expf(-x)); }
__device__ __forceinline__ float dot4(float4 a, float4 b) {
    return fmaf(a.x, b.x, fmaf(a.y, b.y, fmaf(a.z, b.z, a.w * b.w)));
}
__device__ __forceinline__ float wred(float v) {
#pragma unroll
    for (int o = 16; o; o >>= 1) v += __shfl_down_sync(0xffffffffu, v, o);
    return v;
}
__device__ __forceinline__ void block_sum2(float& a, float& b, float* sRed) {
#pragma unroll
    for (int o = 16; o; o >>= 1) {
        a += __shfl_down_sync(0xffffffffu, a, o);
        b += __shfl_down_sync(0xffffffffu, b, o);
    }
    __syncthreads();
    const int w = threadIdx.x >> 5;
    if ((threadIdx.x & 31) == 0) { sRed[w] = a; sRed[16 + w] = b; }
    __syncthreads();
    float ra = 0.f, rb = 0.f;
#pragma unroll
    for (int i = 0; i < 16; i++) { ra += sRed[i]; rb += sRed[16 + i]; }
    a = ra; b = rb;
}

__global__ void zero_flags_kernel() {
    int t = threadIdx.x;
    if (t < NBLK) g_lineA[t][0] = 0u;
    if (t < BB)   g_lineB[t][0] = 0u;
}

// ====================================================================
__global__ void __launch_bounds__(NTHR, 1)
sgru_main(const float* __restrict__ x,       const float* __restrict__ h_in,
          const float* __restrict__ v_in,    const float* __restrict__ dU_in,
          const float* __restrict__ te_in,   const float* __restrict__ tE_in,
          const float* __restrict__ x2h_w,   const float* __restrict__ x2h_b,
          const float* __restrict__ h2h_w,   const float* __restrict__ h2h_b,
          const float* __restrict__ lnx_g,   const float* __restrict__ lnx_b,
          const float* __restrict__ lnh_g,   const float* __restrict__ lnh_b,
          const float* __restrict__ h2mod_w, const float* __restrict__ h2mod_b,
          const float* __restrict__ m2r_w,   const float* __restrict__ m2r_b,
          const float* __restrict__ m2s_w,   const float* __restrict__ m2s_b,
          const float* __restrict__ m2m_w,   const float* __restrict__ m2m_b,
          const float* __restrict__ alpha_p, const float* __restrict__ tauU_p,
          float* __restrict__ out)
{
    extern __shared__ float sm[];
    const int tid = threadIdx.x;
    const int bk  = blockIdx.x;
    const int wid = tid >> 5, lid = tid & 31;
    const int b   = bk >> 4;          // batch
    const int bg  = bk & 15;          // index within batch group
    const bool isGate = (bg == 0);
    const int i0  = bg * 32;          // first owned i-row
    const int g   = tid >> 7;         // row subgroup 0..3
    const int q   = tid & 127;        // quad index

    // zo ownership: gate -> rows 0..3; block bg>=1 -> rows 4+(bg-1)*68 .. +68
    const int zbase = isGate ? 0 : (4 + (bg - 1) * 68);
    const int nz    = isGate ? 4 : 68;

    float*  sH    = sm + S_H;
    float*  sHfw  = sm + S_HFW;
    float*  sTe   = sm + S_TE;
    float*  sWX   = sm + S_WX;
    float*  sFwP  = sm + S_FWP;
    float*  sMod  = sm + S_MOD;
    float*  sZV   = sm + S_ZV;
    float*  sDV   = sm + S_DV;
    float*  sScal = sm + S_SCAL;
    float*  sRed  = sm + S_RED;
    float4* sTE4  = (float4*)(sm + S_TEM);
    float4* sZW4  = (float4*)(sm + S_ZW);
    float4* sH4   = (float4*)sH;
    float4* sHfw4 = (float4*)sHfw;
    float4* sTe4  = (float4*)sTe;

    const float spa     = log1pf(expf(alpha_p[0]));
    const float inv_spe = 1.f / (spa + 1e-8f);
    const float tau     = 1.f / (1.f + expf(-tauU_p[0]));
    const float omtau   = 1.f - tau;

    // ================= PROLOGUE A: g_wx = LN(x @ x2h^T + b) =================
    {
        float* sX    = sm;           // [4][256]
        float* wtile = sm + 1024;    // [1536][9]
        const int rg0 = bk * 4;

        float acc[4][3];
#pragma unroll
        for (int r = 0; r < 4; r++)
#pragma unroll
            for (int p = 0; p < 3; p++) acc[r][p] = 0.f;

        for (int idx = tid; idx < 4 * IN_DIM; idx += NTHR)
            sX[idx] = x[(size_t)rg0 * IN_DIM + idx];

        for (int ct = 0; ct < 32; ++ct) {
            const int c0 = ct * 8;
            __syncthreads();
            for (int idx = tid; idx < H3 * 8; idx += NTHR) {
                int kl = idx >> 3, c = idx & 7;
                wtile[kl * 9 + c] = x2h_w[(size_t)kl * IN_DIM + c0 + c];
            }
            __syncthreads();
            float xv[4][8];
#pragma unroll
            for (int r = 0; r < 4; r++)
#pragma unroll
                for (int c = 0; c < 8; c++) xv[r][c] = sX[r * IN_DIM + c0 + c];
#pragma unroll
            for (int p = 0; p < 3; p++) {
                const int kk = tid + NTHR * p;
                float wv[8];
#pragma unroll
                for (int c = 0; c < 8; c++) wv[c] = wtile[kk * 9 + c];
#pragma unroll
                for (int r = 0; r < 4; r++)
#pragma unroll
                    for (int c = 0; c < 8; c++)
                        acc[r][p] = fmaf(wv[c], xv[r][c], acc[r][p]);
            }
        }
#pragma unroll
        for (int p = 0; p < 3; p++) {
            const float bq = x2h_b[tid + NTHR * p];
#pragma unroll
            for (int r = 0; r < 4; r++) acc[r][p] += bq;
        }
#pragma unroll
        for (int r = 0; r < 4; r++) {
            float s1 = 0.f, s2 = 0.f;
#pragma unroll
            for (int p = 0; p < 3; p++) { float v = acc[r][p]; s1 += v; s2 = fmaf(v, v, s2); }
            block_sum2(s1, s2, sRed);
            const float mu   = s1 * (1.f / H3);
            const float rstd = rsqrtf(s2 * (1.f / H3) - mu * mu + 1e-5f);
            float* wrow = g_wx + (size_t)(rg0 + r) * H3;
#pragma unroll
            for (int p = 0; p < 3; p++) {
                const int kk = tid + NTHR * p;
                wrow[kk] = (acc[r][p] - mu) * rstd * lnx_g[kk] + lnx_b[kk];
            }
        }
        __syncthreads();
    }

    // ================= PROLOGUE B: persistent state =================
    float4 rDU4[8], w4r[8];
    float vb, lg0, lg1, lg2, lb0, lb1, lb2;
    {
#pragma unroll
        for (int r = 0; r < 8; r++) {
            const int rloc = g * 8 + r;
            const int i    = i0 + rloc;
            const size_t g4 = (size_t)(b * HH + i) * 128 + q;
            rDU4[r] = ((const float4*)dU_in)[g4];
            sTE4[rloc * 128 + q] = ((const float4*)tE_in)[g4];
            w4r[r] = ((const float4*)(h2h_w + (size_t)(2 * HH + i) * HH))[q];
        }
        if (isGate) {
            // 4 zo rows + 64 mod rows cached
            for (int idx = tid; idx < 4 * 128; idx += NTHR) {
                const int wloc = idx >> 7, c = idx & 127;
                sZW4[idx] = ((const float4*)(h2h_w + (size_t)wloc * HH))[c];
            }
            for (int idx = tid; idx < 64 * 128; idx += NTHR) {
                const int m = idx >> 7, c = idx & 127;
                sZW4[4 * 128 + idx] = ((const float4*)(h2mod_w + (size_t)m * HH))[c];
            }
        } else {
            for (int idx = tid; idx < 68 * 128; idx += NTHR) {
                const int wloc = idx >> 7, c = idx & 127;
                sZW4[idx] = ((const float4*)(h2h_w + (size_t)(zbase + wloc) * HH))[c];
            }
        }
        sH [tid] = h_in [b * HH + tid];
        sTe[tid] = te_in[b * HH + tid];
        vb  = v_in[b * HH + tid];
        lg0 = lnh_g[tid];          lb0 = lnh_b[tid];
        lg1 = lnh_g[HH + tid];     lb1 = lnh_b[HH + tid];
        lg2 = lnh_g[2 * HH + tid]; lb2 = lnh_b[2 * HH + tid];
        __syncthreads();
    }

    // ================= MAIN LOOP =================
    for (int it = 0; it <= T_STEPS; ++it) {
        const bool last = (it == T_STEPS);
        float* whb = g_whbuf[it & 1];

        if (!last) {
            // ---- wx(t) prefetch into smem ----
            const float* wxg = g_wx + (size_t)it * (BB * H3) + b * H3;
#pragma unroll
            for (int p = 0; p < 3; p++)
                sWX[tid + NTHR * p] = __ldcg(&wxg[tid + NTHR * p]);

            // ---- zo GEMM ----
            if (isGate) {
                if (wid < 4) {
                    const int k = wid;
                    float a = 0.f;
#pragma unroll
                    for (int c = 0; c < 4; c++)
                        a += dot4(sZW4[wid * 128 + lid + 32 * c], sH4[lid + 32 * c]);
                    a = wred(a);
                    if (lid == 0) {
                        const float v = a + h2h_b[k];
                        __stcg(&whb[b * H3 + k], v);
                        sZV[wid] = v;
                    }
                }
            } else {
                const int nr    = (wid < 4) ? 5 : 4;
                const int start = (wid < 4) ? wid * 5 : 20 + (wid - 4) * 4;
                for (int rr = 0; rr < nr; rr++) {
                    const int wloc = start + rr;
                    const int k    = zbase + wloc;
                    float a = 0.f;
#pragma unroll
                    for (int c = 0; c < 4; c++)
                        a += dot4(sZW4[wloc * 128 + lid + 32 * c], sH4[lid + 32 * c]);
                    a = wred(a);
                    if (lid == 0) {
                        const float v = a + h2h_b[k];
                        __stcg(&whb[b * H3 + k], v);
                        sZV[wloc] = v;
                    }
                }
            }
        }

        // ---- wait flagB (scalars of step it-1); gate has them locally ----
        if (it > 0 && !isGate) {
            wait_line(&g_lineB[b][0], (unsigned)it);
            if (tid < 3) sScal[tid] = __ldcg((const float*)&g_lineB[b][1 + tid]);
            __syncthreads();
        }

        // ---- trace update (step it-1) + fused dv partials ----
        {
            float rb = 0.f, sb = 0.f, mb = 0.f;
            if (it > 0) { rb = sScal[0]; sb = sScal[1]; mb = sScal[2]; }
            const float oms = 1.f - sb;
            const float tm  = tau * mb;
            const float4 teo4 = sTe4 [q];
            const float4 hf4  = sHfw4[q];
            const float4 h4   = sH4  [q];
#pragma unroll
            for (int r = 0; r < 8; r++) {
                const int rloc = g * 8 + r;
                if (it > 0) {
                    const float hfi = sHfw[i0 + rloc];
                    const float tei = sTe [i0 + rloc];
                    float4 t4 = sTE4[rloc * 128 + q];
                    t4.x = oms * t4.x + sb * (hfi * teo4.x - tei * hf4.x);
                    t4.y = oms * t4.y + sb * (hfi * teo4.y - tei * hf4.y);
                    t4.z = oms * t4.z + sb * (hfi * teo4.z - tei * hf4.z);
                    t4.w = oms * t4.w + sb * (hfi * teo4.w - tei * hf4.w);
                    sTE4[rloc * 128 + q] = t4;
                    const float4 w = w4r[r];
                    float4 d = rDU4[r];
                    d.x = fmaxf(fminf(omtau * d.x + tm * t4.x,  fmaxf(1.f - w.x, 0.f) * inv_spe), -fmaxf(1.f + w.x, 0.f) * inv_spe);
                    d.y = fmaxf(fminf(omtau * d.y + tm * t4.y,  fmaxf(1.f - w.y, 0.f) * inv_spe), -fmaxf(1.f + w.y, 0.f) * inv_spe);
                    d.z = fmaxf(fminf(omtau * d.z + tm * t4.z,  fmaxf(1.f - w.z, 0.f) * inv_spe), -fmaxf(1.f + w.z, 0.f) * inv_spe);
                    d.w = fmaxf(fminf(omtau * d.w + tm * t4.w,  fmaxf(1.f - w.w, 0.f) * inv_spe), -fmaxf(1.f + w.w, 0.f) * inv_spe);
                    rDU4[r] = d;
                }
                if (!last) {
                    const float4 w = w4r[r];
                    const float4 d = rDU4[r];
                    float p = (w.x + spa * d.x) * h4.x;
                    p = fmaf(w.y + spa * d.y, h4.y, p);
                    p = fmaf(w.z + spa * d.z, h4.z, p);
                    p = fmaf(w.w + spa * d.w, h4.w, p);
                    p = wred(p);
                    if (lid == 0) sFwP[rloc * 4 + (wid & 3)] = p;
                }
            }
            __syncthreads();
            if (it > 0) {
                const float tnew = (1.f - rb) * sTe[tid] + rb * sHfw[tid];
                __syncthreads();
                sTe[tid] = tnew;
            }
        }

        if (last) break;

        // ---- dv combine + local LN-stat partial + publish flagA (with stats) ----
        if (tid < 32) {
            const float v = sFwP[tid * 4] + sFwP[tid * 4 + 1] + sFwP[tid * 4 + 2] + sFwP[tid * 4 + 3];
            const int k = 2 * HH + i0 + tid;
            const float dv = v + h2h_b[k];
            __stcg(&whb[b * H3 + k], dv);
            sDV[tid] = dv;
            // stats over this block's produced wh values
            float s1 = dv, s2 = dv * dv;
            for (int kk = lid; kk < nz; kk += 32) {
                const float zv = sZV[kk];
                s1 += zv; s2 = fmaf(zv, zv, s2);
            }
#pragma unroll
            for (int o = 16; o; o >>= 1) {
                s1 += __shfl_down_sync(0xffffffffu, s1, o);
                s2 += __shfl_down_sync(0xffffffffu, s2, o);
            }
            if (lid == 0) { sRed[0] = s1; sRed[1] = s2; }
        }
        __syncthreads();
        if (tid == 0) {
            __stcg((float*)&g_lineA[bk][1], sRed[0]);
            __stcg((float*)&g_lineA[bk][2], sRed[1]);
            st_rel(&g_lineA[bk][0], (unsigned)(it + 1));
        }

        // ---- shadow (non-gate): dUs(it-1) store ----
        if (!isGate && it > 0) {
            float4* dus4 = (float4*)(out + OUT_DUS + (size_t)(it - 1) * (BB * HH * HH));
#pragma unroll
            for (int r = 0; r < 8; r++)
                __stcs(&dus4[(size_t)(b * HH + i0 + g * 8 + r) * 128 + q], rDU4[r]);
        }

        // ---- wait all 16 producers of this batch + gather LN stats ----
        if (tid < 32) {
            const unsigned* pl = &g_lineA[b * 16 + (lid & 15)][0];
            for (;;) {
                int ok = (ld_acq(pl) >= (unsigned)(it + 1));
                if (__all_sync(0xffffffffu, ok)) break;
            }
            float a1 = 0.f, a2 = 0.f;
            if (lid < 16) {
                a1 = __ldcg((const float*)&g_lineA[b * 16 + lid][1]);
                a2 = __ldcg((const float*)&g_lineA[b * 16 + lid][2]);
            }
#pragma unroll
            for (int o = 16; o; o >>= 1) {
                a1 += __shfl_down_sync(0xffffffffu, a1, o);
                a2 += __shfl_down_sync(0xffffffffu, a2, o);
            }
            if (lid == 0) { sRed[0] = a1; sRed[1] = a2; }
        }
        __syncthreads();

        // ---- gates (redundant per batch): whb load + LN + gates -> sH/sHfw ----
        {
            const float mu = sRed[0] * (1.f / H3);
            const float rs = rsqrtf(sRed[1] * (1.f / H3) - mu * mu + 1e-5f);
            const float* whrow = whb + b * H3;
            const float p0 = __ldcg(&whrow[tid]);
            const float p1 = __ldcg(&whrow[HH + tid]);
            const float p2 = __ldcg(&whrow[2 * HH + tid]);
            const float pz = (p0 - mu) * rs * lg0 + lb0 + sWX[tid];
            const float po = (p1 - mu) * rs * lg1 + lb1 + sWX[HH + tid];
            const float pd = (p2 - mu) * rs * lg2 + lb2 + sWX[2 * HH + tid];
            const float z = sigm(pz);
            const float o = sigm(po);
            vb = (1.f - z) * vb + z * pd;
            const float nh = fmaxf(vb, 0.f);
            const float hf = o * nh;
            sH  [tid] = nh;
            sHfw[tid] = hf;
            if (isGate)
                out[OUT_OUTS + (size_t)it * (BB * HH) + b * HH + tid] = nh;
        }
        __syncthreads();

        // ---- gate only: mod + scalars -> flagB; then shadow dUs ----
        if (isGate) {
            const float4* nh4 = (const float4*)sH;
            float4 nv[4];
#pragma unroll
            for (int c = 0; c < 4; c++) nv[c] = nh4[lid + 32 * c];
#pragma unroll
            for (int rr = 0; rr < 6; rr++) {
                const int row = wid * 6 + rr;
                float a = 0.f;
                if (row < 64) {
#pragma unroll
                    for (int c = 0; c < 4; c++)
                        a += dot4(sZW4[(4 + row) * 128 + lid + 32 * c], nv[c]);
                } else {
                    const float4* mw = (const float4*)(h2mod_w + (size_t)row * HH);
#pragma unroll
                    for (int c = 0; c < 4; c++) a += dot4(__ldcg(&mw[lid + 32 * c]), nv[c]);
                }
                a = wred(a);
                if (lid == 0) {
                    const float mv = fmaxf(a + h2mod_b[row], 0.f);
                    sMod[row] = mv;
                    out[OUT_MODS + (size_t)it * (BB * 96) + b * 96 + row] = mv;
                }
            }
            __syncthreads();
            if (wid < 3) {
                const float* ww = (wid == 0) ? m2r_w : (wid == 1) ? m2s_w : m2m_w;
                const float bb0 = (wid == 0) ? m2r_b[0] : (wid == 1) ? m2s_b[0] : m2m_b[0];
                float a = wred(sMod[wid * 32 + lid] * ww[lid]);
                if (lid == 0) {
                    float val;
                    if (wid == 0) {
                        val = sigm(a + bb0);
                        out[OUT_RS + (size_t)it * BB + b] = val;
                    } else if (wid == 1) {
                        val = sigm(a + bb0);
                        out[OUT_SS + (size_t)it * BB + b] = val;
                    } else {
                        const float mm = a + bb0;
                        val = mm - tanhf(mm);
                        out[OUT_MS + (size_t)it * BB + b] = val;
                    }
                    sScal[wid] = val;
                    __stcg((float*)&g_lineB[b][1 + wid], val);
                }
            }
            __syncthreads();
            if (tid == 0) st_rel(&g_lineB[b][0], (unsigned)(it + 1));
            if (it > 0) {
                float4* dus4 = (float4*)(out + OUT_DUS + (size_t)(it - 1) * (BB * HH * HH));
#pragma unroll
                for (int r = 0; r < 8; r++)
                    __stcs(&dus4[(size_t)(b * HH + i0 + g * 8 + r) * 128 + q], rDU4[r]);
            }
        }
    }

    // ================= EPILOGUE =================
    {
        float4* dus4 = (float4*)(out + OUT_DUS + (size_t)(T_STEPS - 1) * (BB * HH * HH));
        float4* duf4 = (float4*)(out + OUT_DUF);
        float4* tem4 = (float4*)(out + OUT_TEMAT);
#pragma unroll
        for (int r = 0; r < 8; r++) {
            const int rloc = g * 8 + r;
            const size_t g4 = (size_t)(b * HH + i0 + rloc) * 128 + q;
            dus4[g4] = rDU4[r];
            duf4[g4] = rDU4[r];
            tem4[g4] = sTE4[rloc * 128 + q];
        }
    }
    if (isGate) {
        out[OUT_V   + b * HH + tid] = vb;
        out[OUT_H   + b * HH + tid] = sH[tid];
        out[OUT_TEF + b * HH + tid] = sTe[tid];
    }
}

// ====================================================================
extern "C" void kernel_launch(void* const* d_in, const int* in_sizes, int n_in,
                              void* d_out, int out_size) {
    const float* x       = (const float*)d_in[0];
    const float* h       = (const float*)d_in[1];
    const float* v       = (const float*)d_in[2];
    const float* dU      = (const float*)d_in[3];
    const float* te      = (const float*)d_in[4];
    const float* tE      = (const float*)d_in[5];
    const float* x2h_w   = (const float*)d_in[6];
    const float* x2h_b   = (const float*)d_in[7];
    const float* h2h_w   = (const float*)d_in[8];
    const float* h2h_b   = (const float*)d_in[9];
    const float* lnx_g   = (const float*)d_in[10];
    const float* lnx_b   = (const float*)d_in[11];
    const float* lnh_g   = (const float*)d_in[12];
    const float* lnh_b   = (const float*)d_in[13];
    const float* h2mod_w = (const float*)d_in[14];
    const float* h2mod_b = (const float*)d_in[15];
    const float* m2r_w   = (const float*)d_in[16];
    const float* m2r_b   = (const float*)d_in[17];
    const float* m2s_w   = (const float*)d_in[18];
    const float* m2s_b   = (const float*)d_in[19];
    const float* m2m_w   = (const float*)d_in[20];
    const float* m2m_b   = (const float*)d_in[21];
    const float* alpha   = (const float*)d_in[22];
    const float* tauU    = (const float*)d_in[23];
    float* out = (float*)d_out;

    const size_t smem = (size_t)SMEM_FLOATS * sizeof(float);
    cudaFuncSetAttribute(sgru_main, cudaFuncAttributeMaxDynamicSharedMemorySize, (int)smem);

    zero_flags_kernel<<<1, 128>>>();
    sgru_main<<<NBLK, NTHR, smem>>>(x, h, v, dU, te, tE,
                                    x2h_w, x2h_b, h2h_w, h2h_b,
                                    lnx_g, lnx_b, lnh_g, lnh_b,
                                    h2mod_w, h2mod_b,
                                    m2r_w, m2r_b, m2s_w, m2s_b, m2m_w, m2m_b,
                                    alpha, tauU, out);
}

// round 17
// speedup vs baseline: 1.1147x; 1.1147x over previous
#include <cuda_runtime.h>
#include <cstdint>

#define T_STEPS 64
#define BB      8
#define IN_DIM  256
#define HH      512
#define H3      1536
#define NBLK    128
#define NTHR    512

// ---------------- output offsets (floats) ----------------
#define OUT_V      0ull
#define OUT_H      4096ull
#define OUT_DUF    8192ull
#define OUT_TEF    2105344ull
#define OUT_TEMAT  2109440ull
#define OUT_OUTS   4206592ull
#define OUT_DUS    4468736ull
#define OUT_MODS   138686464ull
#define OUT_SS     138735616ull
#define OUT_MS     138736128ull
#define OUT_RS     138736640ull

// ---------------- smem layout (float index) ----------------
#define S_TEM  0        /* [32][512] trace_E rows (batch-local) */
#define S_ZW   16384    /* [64][512] zo weight rows */
#define S_H    49152    /* [512] h_b */
#define S_HFW  49664    /* [512] hfw_b */
#define S_TE   50176    /* [512] te_b */
#define S_WX   50688    /* [1536] wx(t) */
#define S_FWP  52224    /* [32][4] */
#define S_MOD  52352    /* [32] pad 64 */
#define S_SCAL 52416    /* r,s,m */
#define S_RED  52432    /* [32] */
#define SMEM_FLOATS 52464
// prologue overlay: sX [0,1024) + wtile [1024,14848) inside S_TEM/S_ZW

// ---------------- device globals ----------------
__device__ float    g_wx[T_STEPS * BB * H3];
__device__ float    g_whbuf[2][BB * H3];
__device__ unsigned g_lineA[NBLK][32];      // [0]=flag (128B padded)
__device__ unsigned g_lineB[BB * 3][32];    // [0]=flag, [1]=value bits

// ---------------- helpers ----------------
__device__ __forceinline__ unsigned ld_acq(const unsigned* p) {
    unsigned v;
    asm volatile("ld.global.acquire.gpu.b32 %0, [%1];" : "=r"(v) : "l"(p) : "memory");
    return v;
}
__device__ __forceinline__ void st_rel(unsigned* p, unsigned v) {
    asm volatile("st.global.release.gpu.b32 [%0], %1;" :: "l"(p), "r"(v) : "memory");
}
__device__ __forceinline__ float sigm(float x) { return 1.f / (1.f + __expf(-x)); }
__device__ __forceinline__ float dot4(float4 a, float4 b) {
    return fmaf(a.x, b.x, fmaf(a.y, b.y, fmaf(a.z, b.z, a.w * b.w)));
}
__device__ __forceinline__ float wred(float v) {
#pragma unroll
    for (int o = 16; o; o >>= 1) v += __shfl_down_sync(0xffffffffu, v, o);
    return v;
}
__device__ __forceinline__ void block_sum2(float& a, float& b, float* sRed) {
#pragma unroll
    for (int o = 16; o; o >>= 1) {
        a += __shfl_down_sync(0xffffffffu, a, o);
        b += __shfl_down_sync(0xffffffffu, b, o);
    }
    __syncthreads();
    const int w = threadIdx.x >> 5;
    if ((threadIdx.x & 31) == 0) { sRed[w] = a; sRed[16 + w] = b; }
    __syncthreads();
    float ra = 0.f, rb = 0.f;
#pragma unroll
    for (int i = 0; i < 16; i++) { ra += sRed[i]; rb += sRed[16 + i]; }
    a = ra; b = rb;
}

__global__ void zero_flags_kernel() {
    int t = threadIdx.x;
    if (t < NBLK)   g_lineA[t][0] = 0u;
    if (t < BB * 3) g_lineB[t][0] = 0u;
}

// ====================================================================
__global__ void __launch_bounds__(NTHR, 1)
sgru_main(const float* __restrict__ x,       const float* __restrict__ h_in,
          const float* __restrict__ v_in,    const float* __restrict__ dU_in,
          const float* __restrict__ te_in,   const float* __restrict__ tE_in,
          const float* __restrict__ x2h_w,   const float* __restrict__ x2h_b,
          const float* __restrict__ h2h_w,   const float* __restrict__ h2h_b,
          const float* __restrict__ lnx_g,   const float* __restrict__ lnx_b,
          const float* __restrict__ lnh_g,   const float* __restrict__ lnh_b,
          const float* __restrict__ h2mod_w, const float* __restrict__ h2mod_b,
          const float* __restrict__ m2r_w,   const float* __restrict__ m2r_b,
          const float* __restrict__ m2s_w,   const float* __restrict__ m2s_b,
          const float* __restrict__ m2m_w,   const float* __restrict__ m2m_b,
          const float* __restrict__ alpha_p, const float* __restrict__ tauU_p,
          float* __restrict__ out)
{
    extern __shared__ float sm[];
    const int tid = threadIdx.x;
    const int bk  = blockIdx.x;
    const int wid = tid >> 5, lid = tid & 31;
    const int b   = bk >> 4;          // batch
    const int bg  = bk & 15;          // index within batch group
    const bool isGate = (bg == 0);
    const bool isScal = (bg < 3);     // scalar blocks: bg = 0(r), 1(s), 2(m)
    const int i0  = bg * 32;          // first owned i-row
    const int g   = tid >> 7;         // row subgroup 0..3
    const int q   = tid & 127;        // quad index

    float*  sH    = sm + S_H;
    float*  sHfw  = sm + S_HFW;
    float*  sTe   = sm + S_TE;
    float*  sWX   = sm + S_WX;
    float*  sFwP  = sm + S_FWP;
    float*  sMod  = sm + S_MOD;
    float*  sScal = sm + S_SCAL;
    float*  sRed  = sm + S_RED;
    float4* sTE4  = (float4*)(sm + S_TEM);
    float4* sZW4  = (float4*)(sm + S_ZW);
    float4* sH4   = (float4*)sH;
    float4* sHfw4 = (float4*)sHfw;
    float4* sTe4  = (float4*)sTe;

    const float spa     = log1pf(expf(alpha_p[0]));
    const float inv_spe = 1.f / (spa + 1e-8f);
    const float tau     = 1.f / (1.f + expf(-tauU_p[0]));
    const float omtau   = 1.f - tau;

    // ================= PROLOGUE A: g_wx = LN(x @ x2h^T + b) =================
    {
        float* sX    = sm;           // [4][256]
        float* wtile = sm + 1024;    // [1536][9]
        const int rg0 = bk * 4;

        float acc[4][3];
#pragma unroll
        for (int r = 0; r < 4; r++)
#pragma unroll
            for (int p = 0; p < 3; p++) acc[r][p] = 0.f;

        for (int idx = tid; idx < 4 * IN_DIM; idx += NTHR)
            sX[idx] = x[(size_t)rg0 * IN_DIM + idx];

        for (int ct = 0; ct < 32; ++ct) {
            const int c0 = ct * 8;
            __syncthreads();
            for (int idx = tid; idx < H3 * 8; idx += NTHR) {
                int kl = idx >> 3, c = idx & 7;
                wtile[kl * 9 + c] = x2h_w[(size_t)kl * IN_DIM + c0 + c];
            }
            __syncthreads();
            float xv[4][8];
#pragma unroll
            for (int r = 0; r < 4; r++)
#pragma unroll
                for (int c = 0; c < 8; c++) xv[r][c] = sX[r * IN_DIM + c0 + c];
#pragma unroll
            for (int p = 0; p < 3; p++) {
                const int kk = tid + NTHR * p;
                float wv[8];
#pragma unroll
                for (int c = 0; c < 8; c++) wv[c] = wtile[kk * 9 + c];
#pragma unroll
                for (int r = 0; r < 4; r++)
#pragma unroll
                    for (int c = 0; c < 8; c++)
                        acc[r][p] = fmaf(wv[c], xv[r][c], acc[r][p]);
            }
        }
#pragma unroll
        for (int p = 0; p < 3; p++) {
            const float bq = x2h_b[tid + NTHR * p];
#pragma unroll
            for (int r = 0; r < 4; r++) acc[r][p] += bq;
        }
#pragma unroll
        for (int r = 0; r < 4; r++) {
            float s1 = 0.f, s2 = 0.f;
#pragma unroll
            for (int p = 0; p < 3; p++) { float v = acc[r][p]; s1 += v; s2 = fmaf(v, v, s2); }
            block_sum2(s1, s2, sRed);
            const float mu   = s1 * (1.f / H3);
            const float rstd = rsqrtf(s2 * (1.f / H3) - mu * mu + 1e-5f);
            float* wrow = g_wx + (size_t)(rg0 + r) * H3;
#pragma unroll
            for (int p = 0; p < 3; p++) {
                const int kk = tid + NTHR * p;
                wrow[kk] = (acc[r][p] - mu) * rstd * lnx_g[kk] + lnx_b[kk];
            }
        }
        __syncthreads();
    }

    // ================= PROLOGUE B: persistent state =================
    float4 rDU4[8], w4r[8];
    float vb, lg0, lg1, lg2, lb0, lb1, lb2;
    {
#pragma unroll
        for (int r = 0; r < 8; r++) {
            const int rloc = g * 8 + r;
            const int i    = i0 + rloc;
            const size_t g4 = (size_t)(b * HH + i) * 128 + q;
            rDU4[r] = ((const float4*)dU_in)[g4];
            sTE4[rloc * 128 + q] = ((const float4*)tE_in)[g4];
            w4r[r] = ((const float4*)(h2h_w + (size_t)(2 * HH + i) * HH))[q];
        }
        for (int idx = tid; idx < 64 * 128; idx += NTHR) {
            const int wloc = idx >> 7, c = idx & 127;
            sZW4[idx] = ((const float4*)(h2h_w + (size_t)(bg * 64 + wloc) * HH))[c];
        }
        sH [tid] = h_in [b * HH + tid];
        sTe[tid] = te_in[b * HH + tid];
        vb  = v_in[b * HH + tid];
        lg0 = lnh_g[tid];          lb0 = lnh_b[tid];
        lg1 = lnh_g[HH + tid];     lb1 = lnh_b[HH + tid];
        lg2 = lnh_g[2 * HH + tid]; lb2 = lnh_b[2 * HH + tid];
        __syncthreads();
    }

    // ================= MAIN LOOP =================
    for (int it = 0; it <= T_STEPS; ++it) {
        const bool last = (it == T_STEPS);
        float* whb = g_whbuf[it & 1];

        if (!last) {
            // ---- wx(t) prefetch into smem ----
            const float* wxg = g_wx + (size_t)it * (BB * H3) + b * H3;
#pragma unroll
            for (int p = 0; p < 3; p++)
                sWX[tid + NTHR * p] = __ldcg(&wxg[tid + NTHR * p]);

            // ---- zo GEMM: 16 warps x 4 rows ----
#pragma unroll
            for (int rr = 0; rr < 4; rr++) {
                const int wloc = wid * 4 + rr;
                const int k    = bg * 64 + wloc;
                float a = 0.f;
#pragma unroll
                for (int c = 0; c < 4; c++)
                    a += dot4(sZW4[wloc * 128 + lid + 32 * c], sH4[lid + 32 * c]);
                a = wred(a);
                if (lid == 0) __stcg(&whb[b * H3 + k], a + h2h_b[k]);
            }
        }

        // ---- wait the 3 scalar lines of this batch (step it-1) ----
        if (it > 0) {
            if (tid < 32) {
                for (;;) {
                    int ok = 1;
                    if (lid < 3) ok = (ld_acq(&g_lineB[b * 3 + lid][0]) >= (unsigned)it);
                    if (__all_sync(0xffffffffu, ok)) break;
                }
            }
            __syncthreads();
            if (tid < 3) sScal[tid] = __ldcg((const float*)&g_lineB[b * 3 + tid][1]);
            __syncthreads();
        }

        // ---- trace update (step it-1) + fused dv partials ----
        {
            float rb = 0.f, sb = 0.f, mb = 0.f;
            if (it > 0) { rb = sScal[0]; sb = sScal[1]; mb = sScal[2]; }
            const float oms = 1.f - sb;
            const float tm  = tau * mb;
            const float4 teo4 = sTe4 [q];
            const float4 hf4  = sHfw4[q];
            const float4 h4   = sH4  [q];
#pragma unroll
            for (int r = 0; r < 8; r++) {
                const int rloc = g * 8 + r;
                if (it > 0) {
                    const float hfi = sHfw[i0 + rloc];
                    const float tei = sTe [i0 + rloc];
                    float4 t4 = sTE4[rloc * 128 + q];
                    t4.x = oms * t4.x + sb * (hfi * teo4.x - tei * hf4.x);
                    t4.y = oms * t4.y + sb * (hfi * teo4.y - tei * hf4.y);
                    t4.z = oms * t4.z + sb * (hfi * teo4.z - tei * hf4.z);
                    t4.w = oms * t4.w + sb * (hfi * teo4.w - tei * hf4.w);
                    sTE4[rloc * 128 + q] = t4;
                    const float4 w = w4r[r];
                    float4 d = rDU4[r];
                    d.x = fmaxf(fminf(omtau * d.x + tm * t4.x,  fmaxf(1.f - w.x, 0.f) * inv_spe), -fmaxf(1.f + w.x, 0.f) * inv_spe);
                    d.y = fmaxf(fminf(omtau * d.y + tm * t4.y,  fmaxf(1.f - w.y, 0.f) * inv_spe), -fmaxf(1.f + w.y, 0.f) * inv_spe);
                    d.z = fmaxf(fminf(omtau * d.z + tm * t4.z,  fmaxf(1.f - w.z, 0.f) * inv_spe), -fmaxf(1.f + w.z, 0.f) * inv_spe);
                    d.w = fmaxf(fminf(omtau * d.w + tm * t4.w,  fmaxf(1.f - w.w, 0.f) * inv_spe), -fmaxf(1.f + w.w, 0.f) * inv_spe);
                    rDU4[r] = d;
                }
                if (!last) {
                    const float4 w = w4r[r];
                    const float4 d = rDU4[r];
                    float p = (w.x + spa * d.x) * h4.x;
                    p = fmaf(w.y + spa * d.y, h4.y, p);
                    p = fmaf(w.z + spa * d.z, h4.z, p);
                    p = fmaf(w.w + spa * d.w, h4.w, p);
                    p = wred(p);
                    if (lid == 0) sFwP[rloc * 4 + (wid & 3)] = p;
                }
            }
            __syncthreads();
            if (it > 0) {
                const float tnew = (1.f - rb) * sTe[tid] + rb * sHfw[tid];
                __syncthreads();
                sTe[tid] = tnew;
            }
        }

        if (last) break;

        // ---- dv combine + publish flagA ----
        if (tid < 32) {
            const float v = sFwP[tid * 4] + sFwP[tid * 4 + 1] + sFwP[tid * 4 + 2] + sFwP[tid * 4 + 3];
            const int k = 2 * HH + i0 + tid;
            __stcg(&whb[b * H3 + k], v + h2h_b[k]);
        }
        __syncthreads();
        if (tid == 0) st_rel(&g_lineA[bk][0], (unsigned)(it + 1));

        // ---- shadow (non-scalar): dUs(it-1) store ----
        if (!isScal && it > 0) {
            float4* dus4 = (float4*)(out + OUT_DUS + (size_t)(it - 1) * (BB * HH * HH));
#pragma unroll
            for (int r = 0; r < 8; r++)
                __stcs(&dus4[(size_t)(b * HH + i0 + g * 8 + r) * 128 + q], rDU4[r]);
        }

        // ---- wait all 16 producers of this batch ----
        if (tid < 32) {
            const unsigned* pl = &g_lineA[b * 16 + (lid & 15)][0];
            for (;;) {
                int ok = (ld_acq(pl) >= (unsigned)(it + 1));
                if (__all_sync(0xffffffffu, ok)) break;
            }
        }
        __syncthreads();

        // ---- gates (redundant per batch): whb load + LN + gates -> sH/sHfw ----
        {
            const float* whrow = whb + b * H3;
            const float p0 = __ldcg(&whrow[tid]);
            const float p1 = __ldcg(&whrow[HH + tid]);
            const float p2 = __ldcg(&whrow[2 * HH + tid]);
            float s1 = p0 + p1 + p2;
            float s2 = fmaf(p0, p0, fmaf(p1, p1, p2 * p2));
            block_sum2(s1, s2, sRed);
            const float mu = s1 * (1.f / H3);
            const float rs = rsqrtf(s2 * (1.f / H3) - mu * mu + 1e-5f);
            const float pz = (p0 - mu) * rs * lg0 + lb0 + sWX[tid];
            const float po = (p1 - mu) * rs * lg1 + lb1 + sWX[HH + tid];
            const float pd = (p2 - mu) * rs * lg2 + lb2 + sWX[2 * HH + tid];
            const float z = sigm(pz);
            const float o = sigm(po);
            vb = (1.f - z) * vb + z * pd;
            const float nh = fmaxf(vb, 0.f);
            const float hf = o * nh;
            sH  [tid] = nh;
            sHfw[tid] = hf;
            if (isGate)
                out[OUT_OUTS + (size_t)it * (BB * HH) + b * HH + tid] = nh;
        }
        __syncthreads();

        // ---- scalar blocks (bg<3): 32 mod rows + one scalar -> own flagB line ----
        if (isScal) {
            const int sc = bg;                 // 0=r, 1=s, 2=m
            const float4* nh4 = (const float4*)sH;
            float4 nv[4];
#pragma unroll
            for (int c = 0; c < 4; c++) nv[c] = nh4[lid + 32 * c];
#pragma unroll
            for (int rr = 0; rr < 2; rr++) {
                const int rl  = wid * 2 + rr;  // 0..31
                const int row = sc * 32 + rl;
                const float4* mw = (const float4*)(h2mod_w + (size_t)row * HH);
                float a = 0.f;
#pragma unroll
                for (int c = 0; c < 4; c++) a += dot4(__ldcg(&mw[lid + 32 * c]), nv[c]);
                a = wred(a);
                if (lid == 0) {
                    const float mv = fmaxf(a + h2mod_b[row], 0.f);
                    sMod[rl] = mv;
                    out[OUT_MODS + (size_t)it * (BB * 96) + b * 96 + row] = mv;
                }
            }
            __syncthreads();
            if (wid == 0) {
                const float* ww = (sc == 0) ? m2r_w : (sc == 1) ? m2s_w : m2m_w;
                const float bb0 = (sc == 0) ? m2r_b[0] : (sc == 1) ? m2s_b[0] : m2m_b[0];
                float a = wred(sMod[lid] * ww[lid]);
                if (lid == 0) {
                    float val;
                    if (sc == 0) {
                        val = sigm(a + bb0);
                        out[OUT_RS + (size_t)it * BB + b] = val;
                    } else if (sc == 1) {
                        val = sigm(a + bb0);
                        out[OUT_SS + (size_t)it * BB + b] = val;
                    } else {
                        const float mm = a + bb0;
                        val = mm - tanhf(mm);
                        out[OUT_MS + (size_t)it * BB + b] = val;
                    }
                    __stcg((float*)&g_lineB[b * 3 + sc][1], val);
                    st_rel(&g_lineB[b * 3 + sc][0], (unsigned)(it + 1));
                }
            }
            // shadow: dUs(it-1)
            if (it > 0) {
                float4* dus4 = (float4*)(out + OUT_DUS + (size_t)(it - 1) * (BB * HH * HH));
#pragma unroll
                for (int r = 0; r < 8; r++)
                    __stcs(&dus4[(size_t)(b * HH + i0 + g * 8 + r) * 128 + q], rDU4[r]);
            }
        }
    }

    // ================= EPILOGUE =================
    {
        float4* dus4 = (float4*)(out + OUT_DUS + (size_t)(T_STEPS - 1) * (BB * HH * HH));
        float4* duf4 = (float4*)(out + OUT_DUF);
        float4* tem4 = (float4*)(out + OUT_TEMAT);
#pragma unroll
        for (int r = 0; r < 8; r++) {
            const int rloc = g * 8 + r;
            const size_t g4 = (size_t)(b * HH + i0 + rloc) * 128 + q;
            dus4[g4] = rDU4[r];
            duf4[g4] = rDU4[r];
            tem4[g4] = sTE4[rloc * 128 + q];
        }
    }
    if (isGate) {
        out[OUT_V   + b * HH + tid] = vb;
        out[OUT_H   + b * HH + tid] = sH[tid];
        out[OUT_TEF + b * HH + tid] = sTe[tid];
    }
}

// ====================================================================
extern "C" void kernel_launch(void* const* d_in, const int* in_sizes, int n_in,
                              void* d_out, int out_size) {
    const float* x       = (const float*)d_in[0];
    const float* h       = (const float*)d_in[1];
    const float* v       = (const float*)d_in[2];
    const float* dU      = (const float*)d_in[3];
    const float* te      = (const float*)d_in[4];
    const float* tE      = (const float*)d_in[5];
    const float* x2h_w   = (const float*)d_in[6];
    const float* x2h_b   = (const float*)d_in[7];
    const float* h2h_w   = (const float*)d_in[8];
    const float* h2h_b   = (const float*)d_in[9];
    const float* lnx_g   = (const float*)d_in[10];
    const float* lnx_b   = (const float*)d_in[11];
    const float* lnh_g   = (const float*)d_in[12];
    const float* lnh_b   = (const float*)d_in[13];
    const float* h2mod_w = (const float*)d_in[14];
    const float* h2mod_b = (const float*)d_in[15];
    const float* m2r_w   = (const float*)d_in[16];
    const float* m2r_b   = (const float*)d_in[17];
    const float* m2s_w   = (const float*)d_in[18];
    const float* m2s_b   = (const float*)d_in[19];
    const float* m2m_w   = (const float*)d_in[20];
    const float* m2m_b   = (const float*)d_in[21];
    const float* alpha   = (const float*)d_in[22];
    const float* tauU    = (const float*)d_in[23];
    float* out = (float*)d_out;

    const size_t smem = (size_t)SMEM_FLOATS * sizeof(float);
    cudaFuncSetAttribute(sgru_main, cudaFuncAttributeMaxDynamicSharedMemorySize, (int)smem);

    zero_flags_kernel<<<1, 128>>>();
    sgru_main<<<NBLK, NTHR, smem>>>(x, h, v, dU, te, tE,
                                    x2h_w, x2h_b, h2h_w, h2h_b,
                                    lnx_g, lnx_b, lnh_g, lnh_b,
                                    h2mod_w, h2mod_b,
                                    m2r_w, m2r_b, m2s_w, m2s_b, m2m_w, m2m_b,
                                    alpha, tauU, out);
}